// round 14
// baseline (speedup 1.0000x reference)
#include <cuda_runtime.h>
#include <cuda_bf16.h>
#include <math.h>
#include <float.h>
#include <stdint.h>

#define BSZ 256
#define DIM 1024
#define SS  32768
#define NT  (SS / 128)

#define GBM 128
#define GBN 128
#define LDW  20    // bf16 operand pitch: 16 data words + 4 pad (80 B)
#define PF32 36    // fp32 staging pitch: 32 data words + 4 pad (144 B)

#define AB_W    (GBM * LDW)    // 2560 words per A bf16 stage
#define BF32_W  (GBN * PF32)   // 4608 words per B fp32 stage
#define BB_W    (GBN * LDW)    // 2560 words per B bf16 stage
#define A_OFF    0
#define BF32_OFF (2 * AB_W * 4)                 // 20480
#define BB_OFF   (BF32_OFF + 3 * BF32_W * 4)    // 75776
#define DSMEM    (BB_OFF + 2 * BB_W * 4)        // 96256 B

// -------- device scratch (allocation-free rule) --------
__device__ float g_pz [(size_t)BSZ * NT];
__device__ float g_ptl[(size_t)BSZ * NT];
__device__ float g_pst[(size_t)BSZ * NT];
__device__ float g_row[BSZ];
__device__ int   g_cnt;

__device__ __forceinline__ void mma16816(float* d, const uint32_t* a, const uint32_t* b)
{
    asm volatile(
        "mma.sync.aligned.m16n8k16.row.col.f32.bf16.bf16.f32 "
        "{%0,%1,%2,%3},{%4,%5,%6,%7},{%8,%9},{%0,%1,%2,%3};"
        : "+f"(d[0]), "+f"(d[1]), "+f"(d[2]), "+f"(d[3])
        : "r"(a[0]), "r"(a[1]), "r"(a[2]), "r"(a[3]), "r"(b[0]), "r"(b[1]));
}
__device__ __forceinline__ uint32_t smem_u32(const void* p) {
    uint32_t a;
    asm("{ .reg .u64 t; cvta.to.shared.u64 t, %1; cvt.u32.u64 %0, t; }" : "=r"(a) : "l"(p));
    return a;
}
#define CP16(dst, src) \
    asm volatile("cp.async.cg.shared.global [%0], [%1], 16;" :: "r"(dst), "l"(src))
#define CP_COMMIT() asm volatile("cp.async.commit_group;" ::: "memory")
#define CP_WAIT(n)  asm volatile("cp.async.wait_group %0;" :: "n"(n) : "memory")

// cvt 16 fp32 (4 float4) -> 2 uint4 of bf16 pairs
__device__ __forceinline__ void cvt16(const float4& c0, const float4& c1,
                                      const float4& c2, const float4& c3,
                                      uint4& o0, uint4& o1)
{
    __nv_bfloat162 t;
    t = __floats2bfloat162_rn(c0.x, c0.y); o0.x = *(unsigned*)&t;
    t = __floats2bfloat162_rn(c0.z, c0.w); o0.y = *(unsigned*)&t;
    t = __floats2bfloat162_rn(c1.x, c1.y); o0.z = *(unsigned*)&t;
    t = __floats2bfloat162_rn(c1.z, c1.w); o0.w = *(unsigned*)&t;
    t = __floats2bfloat162_rn(c2.x, c2.y); o1.x = *(unsigned*)&t;
    t = __floats2bfloat162_rn(c2.z, c2.w); o1.y = *(unsigned*)&t;
    t = __floats2bfloat162_rn(c3.x, c3.y); o1.z = *(unsigned*)&t;
    t = __floats2bfloat162_rn(c3.z, c3.w); o1.w = *(unsigned*)&t;
}

// ---------------------------------------------------------------------------
// Fully fused, zero pre-pass: A fp32 from x via LDG->reg->bf16 STS (shadow),
// gathered B fp32 rows via 3-stage cp.async -> shadow bf16 conversion,
// bf16 HMMA GEMM, bias + masked-softmax loss partials.
// grid (2, 256), 256 thr (8 warps, 2m x 4n), warp tile 64x32, BK=32.
// One __syncthreads per mainloop iteration.
// ---------------------------------------------------------------------------
__global__ __launch_bounds__(256, 2) void fused_gemm_kernel(
    const float* __restrict__ x,
    const float* __restrict__ weight, const float* __restrict__ bias,
    const int* __restrict__ sid,
    const float* __restrict__ targets, const int* __restrict__ san)
{
    extern __shared__ char dyn[];
    uint32_t* sAb   = (uint32_t*)(dyn + A_OFF);     // [2][128][20] bf16 pairs
    float*    sBf32 = (float*)(dyn + BF32_OFF);     // [3][128][36] fp32
    uint32_t* sBb16 = (uint32_t*)(dyn + BB_OFF);    // [2][128][20] bf16 pairs
    __shared__ float sbias[GBN];
    __shared__ int   srid[GBN];

    const int tid  = threadIdx.x;
    const int m0   = blockIdx.x * GBM;
    const int n0   = blockIdx.y * GBN;
    const int bn   = blockIdx.y;
    const int wid  = tid >> 5;
    const int lane = tid & 31;
    const int wm   = (wid & 1) * 64;
    const int wn   = (wid >> 1) * 32;
    const int lr   = lane >> 2;
    const int lc   = lane & 3;

    if (blockIdx.x == 0 && blockIdx.y == 0 && tid == 0) g_cnt = 0;

    if (tid < GBN) {
        int r = __ldg(&sid[n0 + tid]);
        srid[tid] = r;
        sbias[tid] = bias[r];
    }
    __syncthreads();

    // shared roles: 2 threads per row
    const int row_ld = tid >> 1;
    const int h_ld   = tid & 1;
    // A LDG from x (fp32, L2-resident): 16 floats / thread / iter
    const float4* gA = (const float4*)(x + (size_t)(m0 + row_ld) * DIM);
    // B cp.async from gathered weight rows (fp32)
    const char* gB = (const char*)(weight + (size_t)srid[row_ld] * DIM);
    const uint32_t base = smem_u32(dyn);
    const uint32_t dB = base + BF32_OFF + (row_ld * PF32 + h_ld * 16) * 4;
    // STS destinations (word indices)
    uint32_t* aDst0 = sAb + row_ld * LDW + h_ld * 8;
    uint32_t* bDst0 = sBb16 + row_ld * LDW + h_ld * 8;

    // B conversion roles: 1 thread per row-half
    const int crow = tid & 127;
    const int ch   = tid >> 7;

    float acc[4][4][4];
#pragma unroll
    for (int i = 0; i < 4; i++)
#pragma unroll
        for (int j = 0; j < 4; j++)
#pragma unroll
            for (int c = 0; c < 4; c++) acc[i][j][c] = 0.f;

    // ---- prologue ----
    // B fp32 stages 0,1 in flight
#pragma unroll
    for (int s = 0; s < 2; s++) {
#pragma unroll
        for (int j = 0; j < 4; j++)
            CP16(dB + s * (BF32_W * 4) + j * 16, gB + s * 128 + h_ld * 64 + j * 16);
        CP_COMMIT();
    }
    // A stage 0: LDG -> cvt -> Abf[0]
    {
        float4 a0 = gA[h_ld * 4 + 0], a1 = gA[h_ld * 4 + 1];
        float4 a2 = gA[h_ld * 4 + 2], a3 = gA[h_ld * 4 + 3];
        uint4 o0, o1;
        cvt16(a0, a1, a2, a3, o0, o1);
        *(uint4*)(aDst0 + 0) = o0;
        *(uint4*)(aDst0 + 4) = o1;
    }
    // B stage 0 -> Bbf[0]
    CP_WAIT(1);
    __syncthreads();
    {
        const float* f = sBf32 + crow * PF32 + ch * 16;
        float4 c0 = *(const float4*)(f + 0);
        float4 c1 = *(const float4*)(f + 4);
        float4 c2 = *(const float4*)(f + 8);
        float4 c3 = *(const float4*)(f + 12);
        uint4 o0, o1;
        cvt16(c0, c1, c2, c3, o0, o1);
        uint32_t* d = sBb16 + crow * LDW + ch * 8;
        *(uint4*)(d + 0) = o0;
        *(uint4*)(d + 4) = o1;
    }

    const int NIT = DIM / 32;   // 32
    for (int it = 0; it < NIT; it++) {
        // prefetch B fp32 stage it+2
        if (it + 2 < NIT) {
            const int pb = (it + 2) % 3;
#pragma unroll
            for (int j = 0; j < 4; j++)
                CP16(dB + pb * (BF32_W * 4) + j * 16, gB + (it + 2) * 128 + h_ld * 64 + j * 16);
        }
        CP_COMMIT();
        CP_WAIT(1);             // B fp32 stage it+1 arrived
        __syncthreads();        // visibility: Abf/Bbf[it&1] STS + B fp32(it+1)

        // issue A LDG for stage it+1 (L2; covered by MMA span)
        float4 a0, a1, a2, a3;
        const bool more = (it + 1 < NIT);
        if (more) {
            const float4* p = gA + (it + 1) * 8 + h_ld * 4;
            a0 = p[0]; a1 = p[1]; a2 = p[2]; a3 = p[3];
        }

        // ---- MMA on Abf[it&1], Bbf[it&1] ----
        const uint32_t* A = sAb + (it & 1) * AB_W;
        const uint32_t* B = sBb16 + (it & 1) * BB_W;
#pragma unroll
        for (int kk = 0; kk < 2; kk++) {
            const int ktw = kk * 8;
            uint32_t af[4][4], bfr[4][2];
#pragma unroll
            for (int mi = 0; mi < 4; mi++) {
                const int row = wm + mi * 16 + lr;
                af[mi][0] = A[row * LDW + ktw + lc];
                af[mi][1] = A[(row + 8) * LDW + ktw + lc];
                af[mi][2] = A[row * LDW + ktw + 4 + lc];
                af[mi][3] = A[(row + 8) * LDW + ktw + 4 + lc];
            }
#pragma unroll
            for (int nj = 0; nj < 4; nj++) {
                const int col = wn + nj * 8 + lr;
                bfr[nj][0] = B[col * LDW + ktw + lc];
                bfr[nj][1] = B[col * LDW + ktw + 4 + lc];
            }
#pragma unroll
            for (int mi = 0; mi < 4; mi++)
#pragma unroll
                for (int nj = 0; nj < 4; nj++)
                    mma16816(acc[mi][nj], af[mi], bfr[nj]);
        }

        // ---- shadow conversions for stage it+1 ----
        if (more) {
            // A regs -> Abf[(it+1)&1]
            {
                uint4 o0, o1;
                cvt16(a0, a1, a2, a3, o0, o1);
                uint32_t* d = sAb + ((it + 1) & 1) * AB_W + row_ld * LDW + h_ld * 8;
                *(uint4*)(d + 0) = o0;
                *(uint4*)(d + 4) = o1;
            }
            // B fp32 smem -> Bbf[(it+1)&1]
            {
                const float* f = sBf32 + ((it + 1) % 3) * BF32_W + crow * PF32 + ch * 16;
                float4 c0 = *(const float4*)(f + 0);
                float4 c1 = *(const float4*)(f + 4);
                float4 c2 = *(const float4*)(f + 8);
                float4 c3 = *(const float4*)(f + 12);
                uint4 o0, o1;
                cvt16(c0, c1, c2, c3, o0, o1);
                uint32_t* d = sBb16 + ((it + 1) & 1) * BB_W + crow * LDW + ch * 8;
                *(uint4*)(d + 0) = o0;
                *(uint4*)(d + 4) = o1;
            }
        }
    }

    // ---------------- fused loss epilogue ----------------
    CP_WAIT(0);
    __syncthreads();
    float* sz  = (float*)dyn;
    float* stl = sz + 512;
    float* sst = stl + 512;
    const int g = wid >> 1;

#pragma unroll
    for (int mi = 0; mi < 4; mi++) {
        const int row0 = m0 + wm + mi * 16 + lr;
        const int row1 = row0 + 8;
        const float* tp0 = targets + (size_t)row0 * SS + n0 + wn + 2 * lc;
        const float* tp1 = targets + (size_t)row1 * SS + n0 + wn + 2 * lc;
        const int*   sp0 = san + (size_t)row0 * SS + n0 + wn + 2 * lc;
        const int*   sp1 = san + (size_t)row1 * SS + n0 + wn + 2 * lc;

        float z0 = 0.f, z1 = 0.f, t0 = 0.f, t1 = 0.f, s0 = 0.f, s1 = 0.f;
#pragma unroll
        for (int nj = 0; nj < 4; nj++) {
            const float b0 = sbias[wn + nj * 8 + 2 * lc];
            const float b1 = sbias[wn + nj * 8 + 2 * lc + 1];
            float2 tv0 = *(const float2*)(tp0 + nj * 8);
            float2 tv1 = *(const float2*)(tp1 + nj * 8);
            int2   sv0 = *(const int2*)(sp0 + nj * 8);
            int2   sv1 = *(const int2*)(sp1 + nj * 8);

            float l00 = acc[mi][nj][0] + b0;
            float l01 = acc[mi][nj][1] + b1;
            float l10 = acc[mi][nj][2] + b0;
            float l11 = acc[mi][nj][3] + b1;

            if (sv0.x) z0 += __expf(l00);
            if (sv0.y) z0 += __expf(l01);
            if (sv1.x) z1 += __expf(l10);
            if (sv1.y) z1 += __expf(l11);

            t0 = fmaf(tv0.x, l00, t0); t0 = fmaf(tv0.y, l01, t0);
            t1 = fmaf(tv1.x, l10, t1); t1 = fmaf(tv1.y, l11, t1);
            s0 += tv0.x + tv0.y;
            s1 += tv1.x + tv1.y;
        }
#pragma unroll
        for (int o = 1; o <= 2; o <<= 1) {
            z0 += __shfl_xor_sync(0xffffffffu, z0, o);
            z1 += __shfl_xor_sync(0xffffffffu, z1, o);
            t0 += __shfl_xor_sync(0xffffffffu, t0, o);
            t1 += __shfl_xor_sync(0xffffffffu, t1, o);
            s0 += __shfl_xor_sync(0xffffffffu, s0, o);
            s1 += __shfl_xor_sync(0xffffffffu, s1, o);
        }
        if (lc == 0) {
            const int r0l = wm + mi * 16 + lr;
            sz [g * 128 + r0l]     = z0;
            sz [g * 128 + r0l + 8] = z1;
            stl[g * 128 + r0l]     = t0;
            stl[g * 128 + r0l + 8] = t1;
            sst[g * 128 + r0l]     = s0;
            sst[g * 128 + r0l + 8] = s1;
        }
    }
    __syncthreads();

    if (tid < GBM) {
        const size_t o = (size_t)(m0 + tid) * NT + bn;
        g_pz [o] = sz [tid] + sz [128 + tid] + sz [256 + tid] + sz [384 + tid];
        g_ptl[o] = stl[tid] + stl[128 + tid] + stl[256 + tid] + stl[384 + tid];
        g_pst[o] = sst[tid] + sst[128 + tid] + sst[256 + tid] + sst[384 + tid];
    }
}

// ---------------------------------------------------------------------------
// Loss per row (256 blocks) + last block computes the mean (atomic counter).
// ---------------------------------------------------------------------------
__global__ __launch_bounds__(256) void loss_kernel(float* __restrict__ out)
{
    const int b = blockIdx.x;
    const int tid = threadIdx.x;
    float z  = g_pz [b * NT + tid];
    float tl = g_ptl[b * NT + tid];
    float st = g_pst[b * NT + tid];
#pragma unroll
    for (int o = 16; o; o >>= 1) {
        z  += __shfl_xor_sync(0xffffffffu, z, o);
        tl += __shfl_xor_sync(0xffffffffu, tl, o);
        st += __shfl_xor_sync(0xffffffffu, st, o);
    }
    __shared__ float rz[8], rtl[8], rst[8];
    __shared__ int slast;
    if ((tid & 31) == 0) { rz[tid >> 5] = z; rtl[tid >> 5] = tl; rst[tid >> 5] = st; }
    __syncthreads();
    if (tid < 32) {
        z  = (tid < 8) ? rz[tid]  : 0.f;
        tl = (tid < 8) ? rtl[tid] : 0.f;
        st = (tid < 8) ? rst[tid] : 0.f;
#pragma unroll
        for (int o = 4; o; o >>= 1) {
            z  += __shfl_xor_sync(0xffffffffu, z, o);
            tl += __shfl_xor_sync(0xffffffffu, tl, o);
            st += __shfl_xor_sync(0xffffffffu, st, o);
        }
        if (tid == 0) {
            g_row[b] = logf(z) * st - tl;
            __threadfence();
            slast = (atomicAdd(&g_cnt, 1) == BSZ - 1);
        }
    }
    __syncthreads();
    if (slast) {   // deterministic: mean over fixed values in fixed order
        __shared__ float red[256];
        __threadfence();
        red[tid] = *((volatile float*)&g_row[tid]);
        __syncthreads();
        for (int off = 128; off; off >>= 1) {
            if (tid < off) red[tid] += red[tid + off];
            __syncthreads();
        }
        if (tid == 0) out[0] = red[0] / (float)BSZ;
    }
}

extern "C" void kernel_launch(void* const* d_in, const int* in_sizes, int n_in,
                              void* d_out, int out_size)
{
    const float* x       = (const float*)d_in[0];
    const float* weight  = (const float*)d_in[1];
    const float* bias    = (const float*)d_in[2];
    const float* targets = (const float*)d_in[3];
    const int*   sid     = (const int*)d_in[4];
    const int*   san     = (const int*)d_in[5];

    cudaFuncSetAttribute(fused_gemm_kernel,
                         cudaFuncAttributeMaxDynamicSharedMemorySize, DSMEM);
    dim3 gg(BSZ / GBM, SS / GBN);   // (2, 256); m fast -> L2 sharing of weight rows
    fused_gemm_kernel<<<gg, 256, DSMEM>>>(x, weight, bias, sid, targets, san);
    loss_kernel<<<BSZ, 256>>>((float*)d_out);
}

// round 16
// speedup vs baseline: 1.0758x; 1.0758x over previous
#include <cuda_runtime.h>
#include <cuda_bf16.h>
#include <math.h>
#include <float.h>
#include <stdint.h>

#define BSZ 256
#define DIM 1024
#define SS  32768
#define NT  (SS / 128)
#define NJOBS 512          // (BSZ/GBM) * (SS/GBN)
#define GRID  296          // 2 CTAs x 148 SMs (<= 2x152 on GB300): all resident

#define GBM 128
#define GBN 128
#define LDW  20    // bf16 smem pitch: 16 data words + 4 pad (80 B)
#define PF32 36    // fp32 staging pitch: 32 data words + 4 pad (144 B)

#define ASTG_W    (GBM * LDW)
#define BF32STG_W (GBN * PF32)
#define BB16STG_W (GBN * LDW)
#define A_OFF    0
#define BF32_OFF (3 * ASTG_W * 4)
#define BB16_OFF (BF32_OFF + 3 * BF32STG_W * 4)
#define DSMEM    (BB16_OFF + 2 * BB16STG_W * 4)   // 106,496 B

// -------- device scratch (allocation-free rule; zero-initialized) --------
__device__ __align__(16) __nv_bfloat16 g_xbf[(size_t)BSZ * DIM];
__device__ float g_pz [(size_t)BSZ * NT];
__device__ float g_ptl[(size_t)BSZ * NT];
__device__ float g_pst[(size_t)BSZ * NT];
__device__ float g_row[BSZ];
__device__ int   g_bar_arr[2];
__device__ int   g_bar_dep[2];
__device__ int   g_cnt;

__device__ __forceinline__ void mma16816(float* d, const uint32_t* a, const uint32_t* b)
{
    asm volatile(
        "mma.sync.aligned.m16n8k16.row.col.f32.bf16.bf16.f32 "
        "{%0,%1,%2,%3},{%4,%5,%6,%7},{%8,%9},{%0,%1,%2,%3};"
        : "+f"(d[0]), "+f"(d[1]), "+f"(d[2]), "+f"(d[3])
        : "r"(a[0]), "r"(a[1]), "r"(a[2]), "r"(a[3]), "r"(b[0]), "r"(b[1]));
}
__device__ __forceinline__ uint32_t smem_u32(const void* p) {
    uint32_t a;
    asm("{ .reg .u64 t; cvta.to.shared.u64 t, %1; cvt.u32.u64 %0, t; }" : "=r"(a) : "l"(p));
    return a;
}
#define CP16(dst, src) \
    asm volatile("cp.async.cg.shared.global [%0], [%1], 16;" :: "r"(dst), "l"(src))
#define CP_COMMIT() asm volatile("cp.async.commit_group;" ::: "memory")
#define CP_WAIT(n)  asm volatile("cp.async.wait_group %0;" :: "n"(n) : "memory")

// Replay-safe grid barrier: two-phase arrive/depart; last departer resets both.
// All GRID CTAs are resident (launch_bounds + smem budget) -> no deadlock.
__device__ __forceinline__ void grid_barrier(int k)
{
    __syncthreads();
    if (threadIdx.x == 0) {
        __threadfence();
        atomicAdd(&g_bar_arr[k], 1);
        while (*((volatile int*)&g_bar_arr[k]) < GRID) __nanosleep(64);
        int d = atomicAdd(&g_bar_dep[k], 1);
        if (d == GRID - 1) {          // everyone has departed the spin
            g_bar_dep[k] = 0;
            g_bar_arr[k] = 0;
            __threadfence();
        }
    }
    __syncthreads();
}

// ---------------------------------------------------------------------------
__global__ __launch_bounds__(256, 2) void fused_all_kernel(
    const float* __restrict__ x,
    const float* __restrict__ weight, const float* __restrict__ bias,
    const int* __restrict__ sid,
    const float* __restrict__ targets, const int* __restrict__ san,
    float* __restrict__ out)
{
    extern __shared__ char dyn[];
    uint32_t* sAp   = (uint32_t*)(dyn + A_OFF);
    float*    sBf32 = (float*)(dyn + BF32_OFF);
    uint32_t* sBb16 = (uint32_t*)(dyn + BB16_OFF);
    __shared__ float sbias[GBN];
    __shared__ int   srid[GBN];

    const int tid  = threadIdx.x;
    const int wid  = tid >> 5;
    const int lane = tid & 31;
    const int wm   = (wid & 1) * 64;
    const int wn   = (wid >> 1) * 32;
    const int lr   = lane >> 2;
    const int lc   = lane & 3;

    // ---------------- phase 0: convert x -> bf16 ----------------
    {
        int i = blockIdx.x * 256 + tid;     // 65536 float4 total
        if (i < BSZ * DIM / 4) {
            float4 v = ((const float4*)x)[i];
            __nv_bfloat162 p0 = __floats2bfloat162_rn(v.x, v.y);
            __nv_bfloat162 p1 = __floats2bfloat162_rn(v.z, v.w);
            uint2 o;
            o.x = *(const unsigned int*)&p0;
            o.y = *(const unsigned int*)&p1;
            ((uint2*)g_xbf)[i] = o;
        }
    }
    grid_barrier(0);

    // ---------------- phase 1: GEMM + loss partials over tile jobs ----------
    const uint32_t base = smem_u32(dyn);
    const int row_ld = tid >> 1;
    const int h_ld   = tid & 1;
    const int crow = tid & 127;
    const int ch   = tid >> 7;

    for (int job = blockIdx.x; job < NJOBS; job += GRID) {
        const int m0 = (job & 1) * GBM;
        const int bn = job >> 1;
        const int n0 = bn * GBN;

        if (tid < GBN) {
            int r = __ldg(&sid[n0 + tid]);
            srid[tid] = r;
            sbias[tid] = bias[r];
        }
        __syncthreads();

        const char* gA = (const char*)(g_xbf + (size_t)(m0 + row_ld) * DIM);
        const char* gB = (const char*)(weight + (size_t)srid[row_ld] * DIM);
        const uint32_t dA = base + A_OFF    + (row_ld * LDW  + h_ld * 8)  * 4;
        const uint32_t dB = base + BF32_OFF + (row_ld * PF32 + h_ld * 16) * 4;

        float acc[4][4][4];
#pragma unroll
        for (int i = 0; i < 4; i++)
#pragma unroll
            for (int j = 0; j < 4; j++)
#pragma unroll
                for (int c = 0; c < 4; c++) acc[i][j][c] = 0.f;

        // prologue: stages 0, 1 in flight
#pragma unroll
        for (int s = 0; s < 2; s++) {
            CP16(dA + s * (ASTG_W * 4),      gA + s * 64 + h_ld * 32);
            CP16(dA + s * (ASTG_W * 4) + 16, gA + s * 64 + h_ld * 32 + 16);
#pragma unroll
            for (int j = 0; j < 4; j++)
                CP16(dB + s * (BF32STG_W * 4) + j * 16, gB + s * 128 + h_ld * 64 + j * 16);
            CP_COMMIT();
        }
        CP_WAIT(1);
        __syncthreads();
        {
            const float* f = sBf32 + 0 * BF32STG_W + crow * PF32 + ch * 16;
            float4 c0 = *(const float4*)(f + 0);
            float4 c1 = *(const float4*)(f + 4);
            float4 c2 = *(const float4*)(f + 8);
            float4 c3 = *(const float4*)(f + 12);
            uint4 o0, o1;
            __nv_bfloat162 t;
            t = __floats2bfloat162_rn(c0.x, c0.y); o0.x = *(unsigned*)&t;
            t = __floats2bfloat162_rn(c0.z, c0.w); o0.y = *(unsigned*)&t;
            t = __floats2bfloat162_rn(c1.x, c1.y); o0.z = *(unsigned*)&t;
            t = __floats2bfloat162_rn(c1.z, c1.w); o0.w = *(unsigned*)&t;
            t = __floats2bfloat162_rn(c2.x, c2.y); o1.x = *(unsigned*)&t;
            t = __floats2bfloat162_rn(c2.z, c2.w); o1.y = *(unsigned*)&t;
            t = __floats2bfloat162_rn(c3.x, c3.y); o1.z = *(unsigned*)&t;
            t = __floats2bfloat162_rn(c3.z, c3.w); o1.w = *(unsigned*)&t;
            uint32_t* d = sBb16 + 0 * BB16STG_W + crow * LDW + ch * 8;
            *(uint4*)(d + 0) = o0;
            *(uint4*)(d + 4) = o1;
        }

        const int NIT = DIM / 32;
        for (int it = 0; it < NIT; it++) {
            const int ps = it + 2;
            if (ps < NIT) {
                const int pb = ps % 3;
                CP16(dA + pb * (ASTG_W * 4),      gA + ps * 64 + h_ld * 32);
                CP16(dA + pb * (ASTG_W * 4) + 16, gA + ps * 64 + h_ld * 32 + 16);
#pragma unroll
                for (int j = 0; j < 4; j++)
                    CP16(dB + pb * (BF32STG_W * 4) + j * 16, gB + ps * 128 + h_ld * 64 + j * 16);
            }
            CP_COMMIT();
            CP_WAIT(1);
            __syncthreads();

            const uint32_t* A = sAp + (it % 3) * ASTG_W;
            const uint32_t* B = sBb16 + (it & 1) * BB16STG_W;
#pragma unroll
            for (int kk = 0; kk < 2; kk++) {
                const int ktw = kk * 8;
                uint32_t af[4][4], bfr[4][2];
#pragma unroll
                for (int mi = 0; mi < 4; mi++) {
                    const int row = wm + mi * 16 + lr;
                    af[mi][0] = A[row * LDW + ktw + lc];
                    af[mi][1] = A[(row + 8) * LDW + ktw + lc];
                    af[mi][2] = A[row * LDW + ktw + 4 + lc];
                    af[mi][3] = A[(row + 8) * LDW + ktw + 4 + lc];
                }
#pragma unroll
                for (int nj = 0; nj < 4; nj++) {
                    const int col = wn + nj * 8 + lr;
                    bfr[nj][0] = B[col * LDW + ktw + lc];
                    bfr[nj][1] = B[col * LDW + ktw + 4 + lc];
                }
#pragma unroll
                for (int mi = 0; mi < 4; mi++)
#pragma unroll
                    for (int nj = 0; nj < 4; nj++)
                        mma16816(acc[mi][nj], af[mi], bfr[nj]);
            }

            if (it + 1 < NIT) {
                const float* f = sBf32 + ((it + 1) % 3) * BF32STG_W + crow * PF32 + ch * 16;
                float4 c0 = *(const float4*)(f + 0);
                float4 c1 = *(const float4*)(f + 4);
                float4 c2 = *(const float4*)(f + 8);
                float4 c3 = *(const float4*)(f + 12);
                uint4 o0, o1;
                __nv_bfloat162 t;
                t = __floats2bfloat162_rn(c0.x, c0.y); o0.x = *(unsigned*)&t;
                t = __floats2bfloat162_rn(c0.z, c0.w); o0.y = *(unsigned*)&t;
                t = __floats2bfloat162_rn(c1.x, c1.y); o0.z = *(unsigned*)&t;
                t = __floats2bfloat162_rn(c1.z, c1.w); o0.w = *(unsigned*)&t;
                t = __floats2bfloat162_rn(c2.x, c2.y); o1.x = *(unsigned*)&t;
                t = __floats2bfloat162_rn(c2.z, c2.w); o1.y = *(unsigned*)&t;
                t = __floats2bfloat162_rn(c3.x, c3.y); o1.z = *(unsigned*)&t;
                t = __floats2bfloat162_rn(c3.z, c3.w); o1.w = *(unsigned*)&t;
                uint32_t* d = sBb16 + ((it + 1) & 1) * BB16STG_W + crow * LDW + ch * 8;
                *(uint4*)(d + 0) = o0;
                *(uint4*)(d + 4) = o1;
            }
        }

        // ---- loss epilogue for this job ----
        CP_WAIT(0);
        __syncthreads();
        float* sz  = (float*)dyn;
        float* stl = sz + 512;
        float* sst = stl + 512;
        const int g = wid >> 1;

#pragma unroll
        for (int mi = 0; mi < 4; mi++) {
            const int row0 = m0 + wm + mi * 16 + lr;
            const int row1 = row0 + 8;
            const float* tp0 = targets + (size_t)row0 * SS + n0 + wn + 2 * lc;
            const float* tp1 = targets + (size_t)row1 * SS + n0 + wn + 2 * lc;
            const int*   sp0 = san + (size_t)row0 * SS + n0 + wn + 2 * lc;
            const int*   sp1 = san + (size_t)row1 * SS + n0 + wn + 2 * lc;

            float z0 = 0.f, z1 = 0.f, t0 = 0.f, t1 = 0.f, s0 = 0.f, s1 = 0.f;
#pragma unroll
            for (int nj = 0; nj < 4; nj++) {
                const float b0 = sbias[wn + nj * 8 + 2 * lc];
                const float b1 = sbias[wn + nj * 8 + 2 * lc + 1];
                float2 tv0 = *(const float2*)(tp0 + nj * 8);
                float2 tv1 = *(const float2*)(tp1 + nj * 8);
                int2   sv0 = *(const int2*)(sp0 + nj * 8);
                int2   sv1 = *(const int2*)(sp1 + nj * 8);

                float l00 = acc[mi][nj][0] + b0;
                float l01 = acc[mi][nj][1] + b1;
                float l10 = acc[mi][nj][2] + b0;
                float l11 = acc[mi][nj][3] + b1;

                if (sv0.x) z0 += __expf(l00);
                if (sv0.y) z0 += __expf(l01);
                if (sv1.x) z1 += __expf(l10);
                if (sv1.y) z1 += __expf(l11);

                t0 = fmaf(tv0.x, l00, t0); t0 = fmaf(tv0.y, l01, t0);
                t1 = fmaf(tv1.x, l10, t1); t1 = fmaf(tv1.y, l11, t1);
                s0 += tv0.x + tv0.y;
                s1 += tv1.x + tv1.y;
            }
#pragma unroll
            for (int o = 1; o <= 2; o <<= 1) {
                z0 += __shfl_xor_sync(0xffffffffu, z0, o);
                z1 += __shfl_xor_sync(0xffffffffu, z1, o);
                t0 += __shfl_xor_sync(0xffffffffu, t0, o);
                t1 += __shfl_xor_sync(0xffffffffu, t1, o);
                s0 += __shfl_xor_sync(0xffffffffu, s0, o);
                s1 += __shfl_xor_sync(0xffffffffu, s1, o);
            }
            if (lc == 0) {
                const int r0l = wm + mi * 16 + lr;
                sz [g * 128 + r0l]     = z0;
                sz [g * 128 + r0l + 8] = z1;
                stl[g * 128 + r0l]     = t0;
                stl[g * 128 + r0l + 8] = t1;
                sst[g * 128 + r0l]     = s0;
                sst[g * 128 + r0l + 8] = s1;
            }
        }
        __syncthreads();

        if (tid < GBM) {
            const size_t o = (size_t)(m0 + tid) * NT + bn;
            g_pz [o] = sz [tid] + sz [128 + tid] + sz [256 + tid] + sz [384 + tid];
            g_ptl[o] = stl[tid] + stl[128 + tid] + stl[256 + tid] + stl[384 + tid];
            g_pst[o] = sst[tid] + sst[128 + tid] + sst[256 + tid] + sst[384 + tid];
        }
        __syncthreads();   // protect aliased smem before next job's prologue
    }

    grid_barrier(1);

    // ---------------- phase 2: per-row loss + mean ----------------
    if (blockIdx.x < BSZ) {
        const int b = blockIdx.x;
        float z  = g_pz [b * NT + tid];
        float tl = g_ptl[b * NT + tid];
        float st = g_pst[b * NT + tid];
#pragma unroll
        for (int o = 16; o; o >>= 1) {
            z  += __shfl_xor_sync(0xffffffffu, z, o);
            tl += __shfl_xor_sync(0xffffffffu, tl, o);
            st += __shfl_xor_sync(0xffffffffu, st, o);
        }
        __shared__ float rz[8], rtl[8], rst[8];
        __shared__ int slast;
        if ((tid & 31) == 0) { rz[tid >> 5] = z; rtl[tid >> 5] = tl; rst[tid >> 5] = st; }
        __syncthreads();
        if (tid < 32) {
            z  = (tid < 8) ? rz[tid]  : 0.f;
            tl = (tid < 8) ? rtl[tid] : 0.f;
            st = (tid < 8) ? rst[tid] : 0.f;
#pragma unroll
            for (int o = 4; o; o >>= 1) {
                z  += __shfl_xor_sync(0xffffffffu, z, o);
                tl += __shfl_xor_sync(0xffffffffu, tl, o);
                st += __shfl_xor_sync(0xffffffffu, st, o);
            }
            if (tid == 0) {
                g_row[b] = logf(z) * st - tl;
                __threadfence();
                slast = (atomicAdd(&g_cnt, 1) == BSZ - 1);
            }
        }
        __syncthreads();
        if (slast) {   // deterministic fixed-order mean; also resets g_cnt
            __shared__ float red[256];
            __threadfence();
            red[tid] = *((volatile float*)&g_row[tid]);
            __syncthreads();
            for (int off = 128; off; off >>= 1) {
                if (tid < off) red[tid] += red[tid + off];
                __syncthreads();
            }
            if (tid == 0) {
                out[0] = red[0] / (float)BSZ;
                g_cnt = 0;
                __threadfence();
            }
        }
    }
}

extern "C" void kernel_launch(void* const* d_in, const int* in_sizes, int n_in,
                              void* d_out, int out_size)
{
    const float* x       = (const float*)d_in[0];
    const float* weight  = (const float*)d_in[1];
    const float* bias    = (const float*)d_in[2];
    const float* targets = (const float*)d_in[3];
    const int*   sid     = (const int*)d_in[4];
    const int*   san     = (const int*)d_in[5];

    cudaFuncSetAttribute(fused_all_kernel,
                         cudaFuncAttributeMaxDynamicSharedMemorySize, DSMEM);
    fused_all_kernel<<<GRID, 256, DSMEM>>>(x, weight, bias, sid, targets, san,
                                           (float*)d_out);
}